// round 4
// baseline (speedup 1.0000x reference)
#include <cuda_runtime.h>
#include <math.h>

#define BB 2
#define TT 32
#define II 2048
#define FF 64
#define TWO_F 128
#define LL 5
#define TM1 (TT-1)
#define NCHUNK 8
#define CHUNK (II/NCHUNK)   // 256

// ---------------- device scratch (no allocations allowed) ----------------
__device__ float g_k[BB*TT*II*FF];          // k_all, 33.5 MB
__device__ float g_sums[BB*TT*2*TWO_F];     // per-(b,t) group sums [bt][2][128]
__device__ float g_esums[BB*TT*2];          // per-(b,t) group eta sums
__device__ float g_c[II];                   // c_i = Wiota[i] . w_eta
__device__ unsigned char g_mask[TT*II];     // group membership per (t,i)
__device__ int g_lbl[BB*TM1];               // sync labels

// ---------------- kernel: zero accumulators ----------------
__global__ void zero_kernel() {
    int idx = blockIdx.x*blockDim.x + threadIdx.x;
    if (idx < BB*TT*2*TWO_F) g_sums[idx] = 0.f;
    if (idx < BB*TT*2)       g_esums[idx] = 0.f;
}

// ---------------- kernel: prep (membership mask + c_i) ----------------
__global__ void prep_kernel(const float* __restrict__ Wiota,
                            const float* __restrict__ w_eta,
                            const int*   __restrict__ perms) {
    int idx = blockIdx.x*blockDim.x + threadIdx.x;
    if (idx < II) {
        float s = 0.f;
        #pragma unroll 8
        for (int f = 0; f < TWO_F; f++) s += Wiota[idx*TWO_F + f]*w_eta[f];
        g_c[idx] = s;
    }
    if (idx < TT*II) {
        int t = idx / II, j = idx % II;
        int i = perms[idx];
        g_mask[t*II + i] = (j < II/2) ? 0 : 1;
    }
}

// ---------------- kernel: k_all = e @ Ws_w^T + Ws_b ----------------
__global__ void k_kernel(const float* __restrict__ e,
                         const float* __restrict__ Ww,
                         const float* __restrict__ Wb) {
    __shared__ float sWt[FF*FF];   // transposed: sWt[k*FF+f] = Ww[f*FF+k]
    __shared__ float sb[FF];
    __shared__ float se[4][FF];
    for (int x = threadIdx.x; x < FF*FF; x += blockDim.x)
        sWt[(x & 63)*FF + (x >> 6)] = Ww[x];
    if (threadIdx.x < FF) sb[threadIdx.x] = Wb[threadIdx.x];
    int r = threadIdx.x >> 6, f = threadIdx.x & 63;
    size_t row = (size_t)blockIdx.x*4 + r;
    se[r][f] = e[row*FF + f];
    __syncthreads();
    float acc = sb[f];
    #pragma unroll 16
    for (int k = 0; k < FF; k++) acc = fmaf(se[r][k], sWt[k*FF + f], acc);
    g_k[row*FF + f] = acc;
}

// ---------------- kernel: main fused attention + eta + group sums ----------------
__global__ void __launch_bounds__(256, 4)
main_kernel(const float* __restrict__ e,
            const float* __restrict__ w_eta,
            float* __restrict__ out) {
    int bid = blockIdx.x;
    int chunk = bid % NCHUNK;
    int bt = bid / NCHUNK;
    int b = bt / TT, t = bt % TT;
    int warp = threadIdx.x >> 5, lid = threadIdx.x & 31;

    __shared__ float wbuf[8][2][TWO_F];
    __shared__ float webuf[8][2];
    __shared__ float s_weta[TWO_F];
    for (int x = threadIdx.x; x < 8*2*TWO_F; x += 256) ((float*)wbuf)[x] = 0.f;
    if (threadIdx.x < 16) ((float*)webuf)[threadIdx.x] = 0.f;
    if (threadIdx.x < TWO_F) s_weta[threadIdx.x] = w_eta[threadIdx.x];
    __syncthreads();

    const int f0 = lid, f1 = lid + 32;
    const size_t base_bt = (size_t)(b*TT + t)*II;

    for (int it = 0; it < CHUNK/8; it++) {
        int i = chunk*CHUNK + it*8 + warp;
        const float* kq = &g_k[(base_bt + (size_t)i)*FF];
        float kq0 = kq[f0], kq1 = kq[f1];
        float sc[LL];
        // l = 0..L-2 read window rows; l = L-1 is self: <kq,kq>
        #pragma unroll
        for (int l = 0; l < LL-1; l++) {
            int tl = t - (LL-1) + l;
            int tlc = tl < 0 ? 0 : tl;
            const float* kw = &g_k[((size_t)(b*TT + tlc)*II + (size_t)i)*FF];
            float p = fmaf(kq0, kw[f0], kq1*kw[f1]);
            #pragma unroll
            for (int o = 16; o > 0; o >>= 1) p += __shfl_xor_sync(0xffffffffu, p, o);
            sc[l] = (tl >= 0) ? p*0.125f : -1e30f;
        }
        {
            float p = fmaf(kq0, kq0, kq1*kq1);
            #pragma unroll
            for (int o = 16; o > 0; o >>= 1) p += __shfl_xor_sync(0xffffffffu, p, o);
            sc[LL-1] = p*0.125f;
        }
        float mx = sc[0];
        #pragma unroll
        for (int l = 1; l < LL; l++) mx = fmaxf(mx, sc[l]);
        float den = 0.f, a[LL];
        #pragma unroll
        for (int l = 0; l < LL; l++) { a[l] = expf(sc[l] - mx); den += a[l]; }
        float inv = 1.f/den;

        float rh0 = 0.f, rh1 = 0.f, e0 = 0.f, e1 = 0.f;
        #pragma unroll
        for (int l = 0; l < LL; l++) {
            int tl = t - (LL-1) + l;
            int tlc = tl < 0 ? 0 : tl;
            const float* ew = &e[((size_t)(b*TT + tlc)*II + (size_t)i)*FF];
            float w0 = ew[f0], w1 = ew[f1];
            float al = a[l]*inv;
            rh0 = fmaf(al, w0, rh0);
            rh1 = fmaf(al, w1, rh1);
            if (l == LL-1) { e0 = w0; e1 = w1; }
        }
        // eta = relu(c_i + r_all . w_eta)
        float p = e0*s_weta[f0] + e1*s_weta[f1] + rh0*s_weta[64+f0] + rh1*s_weta[64+f1];
        #pragma unroll
        for (int o = 16; o > 0; o >>= 1) p += __shfl_xor_sync(0xffffffffu, p, o);
        float eta = fmaxf(0.f, p + g_c[i]);
        int g = g_mask[t*II + i];
        wbuf[warp][g][f0]      += eta*e0;
        wbuf[warp][g][f1]      += eta*e1;
        wbuf[warp][g][64+f0]   += eta*rh0;
        wbuf[warp][g][64+f1]   += eta*rh1;
        if (lid == 0) webuf[warp][g] += eta;

        if (t == TT-1) {
            float* o_r = out + ((size_t)b*II + (size_t)i)*TWO_F;
            o_r[f0] = e0; o_r[f1] = e1; o_r[64+f0] = rh0; o_r[64+f1] = rh1;
        }
    }
    __syncthreads();
    // block reduce -> global atomics
    int x = threadIdx.x;   // 0..255 covers 2 groups * 128 f
    float v = 0.f;
    #pragma unroll
    for (int w = 0; w < 8; w++) v += ((float*)wbuf)[w*256 + x];
    atomicAdd(&g_sums[bt*256 + x], v);
    if (threadIdx.x < 2) {
        float s = 0.f;
        #pragma unroll
        for (int w = 0; w < 8; w++) s += webuf[w][threadIdx.x];
        atomicAdd(&g_esums[bt*2 + threadIdx.x], s);
    }
}

// ---------------- kernel: sync labels ----------------
__global__ void label_kernel(const float* __restrict__ e,
                             const int* __restrict__ close_idx) {
    int row = blockIdx.x;                 // b*(T-1)+t
    int b = row / TM1, t = row % TM1;
    int cidx = close_idx[0];
    __shared__ int sp[256], sn[256];
    int cp = 0, cn = 0;
    for (int i = threadIdx.x; i < II; i += 256) {
        float c0 = e[((size_t)(b*TT + t)*II + i)*FF + cidx];
        float c1 = e[((size_t)(b*TT + t + 1)*II + i)*FF + cidx];
        float r = logf(c1/(c0 + 1e-8f));
        cp += (r > 0.f); cn += (r < 0.f);
    }
    sp[threadIdx.x] = cp; sn[threadIdx.x] = cn;
    __syncthreads();
    for (int s = 128; s > 0; s >>= 1) {
        if (threadIdx.x < s) { sp[threadIdx.x] += sp[threadIdx.x+s]; sn[threadIdx.x] += sn[threadIdx.x+s]; }
        __syncthreads();
    }
    if (threadIdx.x == 0) {
        float pr = sp[0]/(float)II, nr = sn[0]/(float)II;
        g_lbl[row] = pr >= 0.6f ? 0 : (nr >= 0.6f ? 1 : 2);
    }
}

// ---------------- kernel: finalize (m_all, losses, m_t) ----------------
__global__ void finalize_kernel(const float* __restrict__ w_M,
                                const float* __restrict__ b_M,
                                const float* __restrict__ W1,
                                const float* __restrict__ b1,
                                const float* __restrict__ W2,
                                const float* __restrict__ b2,
                                float* __restrict__ out) {
    __shared__ float sm[BB*TT*TWO_F];     // m_all, 32 KB
    __shared__ float a1s[BB*TT], a2s[BB*TT];
    __shared__ float red[8];
    __shared__ float s_lossc;
    int tid = threadIdx.x;
    int warp = tid >> 5, lid = tid & 31;

    // m_all = (sum1+sum2)/(esum1+esum2+1e-6)
    for (int x = tid; x < BB*TT*TWO_F; x += 256) {
        int bt = x >> 7, f = x & 127;
        float s  = g_sums[bt*256 + f] + g_sums[bt*256 + 128 + f];
        float es = g_esums[bt*2] + g_esums[bt*2 + 1];
        sm[x] = s/(es + 1e-6f);
    }
    // a1/a2: l2-normalized subset means dotted with w_M halves. Warp per bt.
    for (int bt = warp; bt < BB*TT; bt += 8) {
        float es1 = g_esums[bt*2] + 1e-6f, es2 = g_esums[bt*2 + 1] + 1e-6f;
        float ss1 = 0.f, d1 = 0.f, ss2 = 0.f, d2 = 0.f;
        #pragma unroll
        for (int k = 0; k < 4; k++) {
            int f = lid + k*32;
            float m1 = g_sums[bt*256 + f]/es1;
            float m2 = g_sums[bt*256 + 128 + f]/es2;
            ss1 = fmaf(m1, m1, ss1); d1 = fmaf(m1, w_M[f], d1);
            ss2 = fmaf(m2, m2, ss2); d2 = fmaf(m2, w_M[128 + f], d2);
        }
        #pragma unroll
        for (int o = 16; o > 0; o >>= 1) {
            ss1 += __shfl_xor_sync(0xffffffffu, ss1, o);
            d1  += __shfl_xor_sync(0xffffffffu, d1,  o);
            ss2 += __shfl_xor_sync(0xffffffffu, ss2, o);
            d2  += __shfl_xor_sync(0xffffffffu, d2,  o);
        }
        if (lid == 0) {
            a1s[bt] = d1/fmaxf(sqrtf(ss1), 1e-12f);
            a2s[bt] = d2/fmaxf(sqrtf(ss2), 1e-12f);
        }
    }
    __syncthreads();

    // contrastive loss
    float bM = b_M[0];
    float lc = 0.f;
    if (tid < BB*TT) {
        int b = tid >> 5, t1 = tid & 31;
        float a1v = a1s[b*TT + t1];
        float sum = 0.f, pos = 0.f;
        for (int t2 = 0; t2 < TT; t2++) {
            float s = a1v + a2s[b*TT + t2] + bM;
            s = fminf(10.f, fmaxf(-10.f, s));
            int d = t1 - t2; if (d < 0) d = -d;
            float wv = expf(s * (1.f/(float)(d + 1)));
            sum += wv;
            if (t2 == t1) pos = wv;
        }
        lc = -logf(pos/(sum + 1e-8f));
    }
    #pragma unroll
    for (int o = 16; o > 0; o >>= 1) lc += __shfl_xor_sync(0xffffffffu, lc, o);
    if (lid == 0) red[warp] = lc;
    __syncthreads();
    if (tid == 0) s_lossc = (red[0] + red[1]) / 64.f;
    __syncthreads();

    // sync loss: warp per (b,t) row of m_prev
    float acc = 0.f;
    for (int row = warp; row < BB*TM1; row += 8) {
        int b = row / TM1, t = row % TM1;
        const float* m = &sm[(b*TT + t)*TWO_F];
        float h[4];
        #pragma unroll
        for (int k = 0; k < 4; k++) {
            int j = lid*4 + k;
            float s = b1[j];
            #pragma unroll 8
            for (int f = 0; f < TWO_F; f++) s = fmaf(m[f], W1[j*TWO_F + f], s);
            h[k] = fmaxf(0.f, s);
        }
        float lg[3];
        #pragma unroll
        for (int c = 0; c < 3; c++) {
            float s = 0.f;
            #pragma unroll
            for (int k = 0; k < 4; k++) s = fmaf(h[k], W2[c*TWO_F + lid*4 + k], s);
            #pragma unroll
            for (int o = 16; o > 0; o >>= 1) s += __shfl_xor_sync(0xffffffffu, s, o);
            lg[c] = s + b2[c];
        }
        float mx = fmaxf(lg[0], fmaxf(lg[1], lg[2]));
        float lse = mx + logf(expf(lg[0]-mx) + expf(lg[1]-mx) + expf(lg[2]-mx));
        if (lid == 0) acc += lse - lg[g_lbl[row]];
    }
    if (lid == 0) red[warp] = acc;
    __syncthreads();
    if (tid == 0) {
        float tot = 0.f;
        #pragma unroll
        for (int w = 0; w < 8; w++) tot += red[w];
        out[BB*II*TWO_F + BB*TWO_F] = s_lossc + tot/(float)(BB*TM1);
    }
    // m_t = m_all[:, T-1]
    if (tid < BB*TWO_F) {
        int b = tid >> 7, f = tid & 127;
        out[BB*II*TWO_F + b*TWO_F + f] = sm[(b*TT + TT-1)*TWO_F + f];
    }
}

// ---------------- launch ----------------
extern "C" void kernel_launch(void* const* d_in, const int* in_sizes, int n_in,
                              void* d_out, int out_size) {
    const float* e      = (const float*)d_in[0];
    // d_in[1] = stockID (identity) unused
    const float* Ws_w   = (const float*)d_in[2];
    const float* Ws_b   = (const float*)d_in[3];
    const float* Wiota  = (const float*)d_in[4];
    const float* w_eta  = (const float*)d_in[5];
    const float* w_M    = (const float*)d_in[6];
    const float* b_M    = (const float*)d_in[7];
    const float* sc_W1  = (const float*)d_in[8];
    const float* sc_b1  = (const float*)d_in[9];
    const float* sc_W2  = (const float*)d_in[10];
    const float* sc_b2  = (const float*)d_in[11];
    const int*   perms  = (const int*)d_in[12];
    const int*   cidx   = (const int*)d_in[13];
    float* out = (float*)d_out;

    zero_kernel<<<64, 256>>>();
    prep_kernel<<<TT*II/256, 256>>>(Wiota, w_eta, perms);
    k_kernel<<<BB*TT*II/4, 256>>>(e, Ws_w, Ws_b);
    main_kernel<<<BB*TT*NCHUNK, 256>>>(e, w_eta, out);
    label_kernel<<<BB*TM1, 256>>>(e, cidx);
    finalize_kernel<<<1, 256>>>(w_M, b_M, sc_W1, sc_b1, sc_W2, sc_b2, out);
}

// round 5
// speedup vs baseline: 1.7183x; 1.7183x over previous
#include <cuda_runtime.h>
#include <math.h>

#define BB 2
#define TT 32
#define II 2048
#define FF 64
#define TWO_F 128
#define LL 5
#define TM1 (TT-1)
#define NCHUNK 8
#define CHUNK (II/NCHUNK)   // 256

// ---------------- device scratch (no allocations allowed) ----------------
__device__ float g_q[BB*TT*II*FF];          // q_all = e@G + v, 33.5 MB
__device__ float g_G[FF*FF];                // G = Ws^T Ws (symmetric)
__device__ float g_v[FF];                   // v = Ws^T b
__device__ float g_sums[BB*TT*2*TWO_F];     // per-(b,t) group sums [bt][2][128]
__device__ float g_esums[BB*TT*2];          // per-(b,t) group eta sums
__device__ float g_c[II];                   // c_i = Wiota[i] . w_eta
__device__ unsigned char g_mask[TT*II];     // group membership per (t,i)
__device__ int g_lbl[BB*TM1];               // sync labels

// ---------------- kernel: zero accumulators ----------------
__global__ void zero_kernel() {
    int idx = blockIdx.x*blockDim.x + threadIdx.x;
    if (idx < BB*TT*2*TWO_F) g_sums[idx] = 0.f;
    if (idx < BB*TT*2)       g_esums[idx] = 0.f;
}

// ---------------- kernel: prep (membership mask + c_i) ----------------
__global__ void prep_kernel(const float* __restrict__ Wiota,
                            const float* __restrict__ w_eta,
                            const int*   __restrict__ perms) {
    int idx = blockIdx.x*blockDim.x + threadIdx.x;
    if (idx < II) {
        float s = 0.f;
        #pragma unroll 8
        for (int f = 0; f < TWO_F; f++) s += Wiota[idx*TWO_F + f]*w_eta[f];
        g_c[idx] = s;
    }
    if (idx < TT*II) {
        int t = idx / II, j = idx % II;
        int i = perms[idx];
        g_mask[t*II + i] = (j < II/2) ? 0 : 1;
    }
}

// ---------------- kernel: G = Ws^T Ws, v = Ws^T b ----------------
__global__ void prepg_kernel(const float* __restrict__ Ww,
                             const float* __restrict__ Wb) {
    int tid = threadIdx.x;
    for (int x = tid; x < FF*FF; x += 256) {
        int j = x >> 6, k = x & 63;
        float s = 0.f;
        #pragma unroll 8
        for (int f = 0; f < FF; f++) s = fmaf(Ww[f*FF + j], Ww[f*FF + k], s);
        g_G[x] = s;
    }
    if (tid < FF) {
        float s = 0.f;
        #pragma unroll 8
        for (int f = 0; f < FF; f++) s = fmaf(Ww[f*FF + tid], Wb[f], s);
        g_v[tid] = s;
    }
}

// ---------------- kernel: q_all = e @ G + v (register-tiled GEMM) ----------------
// grid = 512, block = 256. Each block: 256 rows, processed 32 rows/iter.
__global__ void __launch_bounds__(256, 2)
q_kernel(const float* __restrict__ e) {
    __shared__ float  sG[FF][FF+1];      // sG[k][f] = G[k][f] (symmetric)
    __shared__ float2 se2[FF][17];       // [k][pair] of 32 rows (16 pairs + pad)
    int tid = threadIdx.x;
    for (int x = tid; x < FF*FF; x += 256) sG[x >> 6][x & 63] = g_G[x];
    int f  = tid & 63;
    int rg = tid >> 6;                   // 0..3, owns rows rg*8 .. rg*8+7
    float vf = g_v[f];
    size_t base = (size_t)blockIdx.x * 256;
    for (int it = 0; it < 8; it++) {
        size_t rb = base + it*32;
        __syncthreads();
        for (int x = tid; x < 32*FF; x += 256) {
            int r = x >> 6, k = x & 63;
            ((float*)&se2[k][0])[r] = e[(rb + (size_t)r)*FF + k];
        }
        __syncthreads();
        float2 a0 = {0.f,0.f}, a1 = {0.f,0.f}, a2 = {0.f,0.f}, a3 = {0.f,0.f};
        #pragma unroll
        for (int k = 0; k < FF; k++) {
            float w = sG[k][f];
            float2 e0 = se2[k][rg*4+0];
            float2 e1 = se2[k][rg*4+1];
            float2 e2 = se2[k][rg*4+2];
            float2 e3 = se2[k][rg*4+3];
            a0.x = fmaf(w, e0.x, a0.x); a0.y = fmaf(w, e0.y, a0.y);
            a1.x = fmaf(w, e1.x, a1.x); a1.y = fmaf(w, e1.y, a1.y);
            a2.x = fmaf(w, e2.x, a2.x); a2.y = fmaf(w, e2.y, a2.y);
            a3.x = fmaf(w, e3.x, a3.x); a3.y = fmaf(w, e3.y, a3.y);
        }
        size_t r0 = rb + rg*8;
        g_q[(r0+0)*FF + f] = a0.x + vf;  g_q[(r0+1)*FF + f] = a0.y + vf;
        g_q[(r0+2)*FF + f] = a1.x + vf;  g_q[(r0+3)*FF + f] = a1.y + vf;
        g_q[(r0+4)*FF + f] = a2.x + vf;  g_q[(r0+5)*FF + f] = a2.y + vf;
        g_q[(r0+6)*FF + f] = a3.x + vf;  g_q[(r0+7)*FF + f] = a3.y + vf;
    }
}

// ---------------- kernel: main fused attention + eta + group sums ----------------
// warp per stock i; f-pair = (2*lid, 2*lid+1); window rows held in registers.
__global__ void __launch_bounds__(256, 4)
main_kernel(const float* __restrict__ e,
            const float* __restrict__ w_eta,
            float* __restrict__ out) {
    int bid = blockIdx.x;
    int chunk = bid % NCHUNK;
    int bt = bid / NCHUNK;
    int b = bt / TT, t = bt % TT;
    int warp = threadIdx.x >> 5, lid = threadIdx.x & 31;

    __shared__ float2 wbuf[8][2][64];    // [warp][group][f-pair]
    __shared__ float  webuf[8][2];
    for (int x = threadIdx.x; x < 8*2*64; x += 256) {
        ((float2*)wbuf)[x] = make_float2(0.f, 0.f);
    }
    if (threadIdx.x < 16) ((float*)webuf)[threadIdx.x] = 0.f;
    __syncthreads();

    // w_eta pairs in registers (warp-uniform loads)
    float2 wa = ((const float2*)w_eta)[lid];        // f = 2lid, 2lid+1
    float2 wb = ((const float2*)w_eta)[32 + lid];   // f = 64+2lid, 64+2lid+1

    const size_t base_bt = (size_t)(b*TT + t)*II;

    for (int it = 0; it < CHUNK/8; it++) {
        int i = chunk*CHUNK + it*8 + warp;
        float2 q2 = ((const float2*)&g_q[(base_bt + (size_t)i)*FF])[lid];
        // load window e rows once into registers
        float2 wrow[LL];
        #pragma unroll
        for (int l = 0; l < LL; l++) {
            int tl = t - (LL-1) + l;
            int tlc = tl < 0 ? 0 : tl;
            wrow[l] = ((const float2*)&e[((size_t)(b*TT + tlc)*II + (size_t)i)*FF])[lid];
        }
        // scores: q . e_window (softmax is invariant to the dropped uniform shift)
        float sc[LL];
        #pragma unroll
        for (int l = 0; l < LL; l++) {
            float p = q2.x*wrow[l].x + q2.y*wrow[l].y;
            #pragma unroll
            for (int o = 16; o > 0; o >>= 1) p += __shfl_xor_sync(0xffffffffu, p, o);
            int tl = t - (LL-1) + l;
            sc[l] = (tl >= 0) ? p*0.125f : -1e30f;
        }
        float mx = sc[0];
        #pragma unroll
        for (int l = 1; l < LL; l++) mx = fmaxf(mx, sc[l]);
        float den = 0.f, a[LL];
        #pragma unroll
        for (int l = 0; l < LL; l++) { a[l] = expf(sc[l] - mx); den += a[l]; }
        float inv = 1.f/den;

        float2 rh = make_float2(0.f, 0.f);
        #pragma unroll
        for (int l = 0; l < LL; l++) {
            float al = a[l]*inv;
            rh.x = fmaf(al, wrow[l].x, rh.x);
            rh.y = fmaf(al, wrow[l].y, rh.y);
        }
        float2 es = wrow[LL-1];   // self row = e[b,t,i,:]

        // eta = relu(c_i + r_all . w_eta)
        float p = es.x*wa.x + es.y*wa.y + rh.x*wb.x + rh.y*wb.y;
        #pragma unroll
        for (int o = 16; o > 0; o >>= 1) p += __shfl_xor_sync(0xffffffffu, p, o);
        float eta = fmaxf(0.f, p + g_c[i]);
        int g = g_mask[t*II + i];
        float2 acc0 = wbuf[warp][g][lid];
        acc0.x = fmaf(eta, es.x, acc0.x);
        acc0.y = fmaf(eta, es.y, acc0.y);
        wbuf[warp][g][lid] = acc0;
        float2 acc1 = wbuf[warp][g][32 + lid];
        acc1.x = fmaf(eta, rh.x, acc1.x);
        acc1.y = fmaf(eta, rh.y, acc1.y);
        wbuf[warp][g][32 + lid] = acc1;
        if (lid == 0) webuf[warp][g] += eta;

        if (t == TT-1) {
            float2* o2 = (float2*)(out + ((size_t)b*II + (size_t)i)*TWO_F);
            o2[lid]      = es;
            o2[32 + lid] = rh;
        }
    }
    __syncthreads();
    // block reduce -> global atomics
    int x = threadIdx.x;
    if (x < 128) {   // 2 groups * 64 pairs
        int g = x >> 6, j = x & 63;
        float2 v = make_float2(0.f, 0.f);
        #pragma unroll
        for (int w = 0; w < 8; w++) {
            float2 u = wbuf[w][g][j];
            v.x += u.x; v.y += u.y;
        }
        atomicAdd(&g_sums[bt*256 + g*128 + 2*j],     v.x);
        atomicAdd(&g_sums[bt*256 + g*128 + 2*j + 1], v.y);
    }
    if (threadIdx.x >= 128 && threadIdx.x < 130) {
        int g = threadIdx.x - 128;
        float s = 0.f;
        #pragma unroll
        for (int w = 0; w < 8; w++) s += webuf[w][g];
        atomicAdd(&g_esums[bt*2 + g], s);
    }
}

// ---------------- kernel: sync labels ----------------
__global__ void label_kernel(const float* __restrict__ e,
                             const int* __restrict__ close_idx) {
    int row = blockIdx.x;                 // b*(T-1)+t
    int b = row / TM1, t = row % TM1;
    int cidx = close_idx[0];
    __shared__ int sp[256], sn[256];
    int cp = 0, cn = 0;
    for (int i = threadIdx.x; i < II; i += 256) {
        float c0 = e[((size_t)(b*TT + t)*II + i)*FF + cidx];
        float c1 = e[((size_t)(b*TT + t + 1)*II + i)*FF + cidx];
        float r = logf(c1/(c0 + 1e-8f));
        cp += (r > 0.f); cn += (r < 0.f);
    }
    sp[threadIdx.x] = cp; sn[threadIdx.x] = cn;
    __syncthreads();
    for (int s = 128; s > 0; s >>= 1) {
        if (threadIdx.x < s) { sp[threadIdx.x] += sp[threadIdx.x+s]; sn[threadIdx.x] += sn[threadIdx.x+s]; }
        __syncthreads();
    }
    if (threadIdx.x == 0) {
        float pr = sp[0]/(float)II, nr = sn[0]/(float)II;
        g_lbl[row] = pr >= 0.6f ? 0 : (nr >= 0.6f ? 1 : 2);
    }
}

// ---------------- kernel: finalize (m_all, losses, m_t) ----------------
__global__ void finalize_kernel(const float* __restrict__ w_M,
                                const float* __restrict__ b_M,
                                const float* __restrict__ W1,
                                const float* __restrict__ b1,
                                const float* __restrict__ W2,
                                const float* __restrict__ b2,
                                float* __restrict__ out) {
    __shared__ float sm[BB*TT*TWO_F];     // m_all, 32 KB
    __shared__ float a1s[BB*TT], a2s[BB*TT];
    __shared__ float red[8];
    __shared__ float s_lossc;
    int tid = threadIdx.x;
    int warp = tid >> 5, lid = tid & 31;

    // m_all = (sum1+sum2)/(esum1+esum2+1e-6)
    for (int x = tid; x < BB*TT*TWO_F; x += 256) {
        int bt = x >> 7, f = x & 127;
        float s  = g_sums[bt*256 + f] + g_sums[bt*256 + 128 + f];
        float es = g_esums[bt*2] + g_esums[bt*2 + 1];
        sm[x] = s/(es + 1e-6f);
    }
    // a1/a2: l2-normalized subset means dotted with w_M halves. Warp per bt.
    for (int bt = warp; bt < BB*TT; bt += 8) {
        float es1 = g_esums[bt*2] + 1e-6f, es2 = g_esums[bt*2 + 1] + 1e-6f;
        float ss1 = 0.f, d1 = 0.f, ss2 = 0.f, d2 = 0.f;
        #pragma unroll
        for (int k = 0; k < 4; k++) {
            int f = lid + k*32;
            float m1 = g_sums[bt*256 + f]/es1;
            float m2 = g_sums[bt*256 + 128 + f]/es2;
            ss1 = fmaf(m1, m1, ss1); d1 = fmaf(m1, w_M[f], d1);
            ss2 = fmaf(m2, m2, ss2); d2 = fmaf(m2, w_M[128 + f], d2);
        }
        #pragma unroll
        for (int o = 16; o > 0; o >>= 1) {
            ss1 += __shfl_xor_sync(0xffffffffu, ss1, o);
            d1  += __shfl_xor_sync(0xffffffffu, d1,  o);
            ss2 += __shfl_xor_sync(0xffffffffu, ss2, o);
            d2  += __shfl_xor_sync(0xffffffffu, d2,  o);
        }
        if (lid == 0) {
            a1s[bt] = d1/fmaxf(sqrtf(ss1), 1e-12f);
            a2s[bt] = d2/fmaxf(sqrtf(ss2), 1e-12f);
        }
    }
    __syncthreads();

    // contrastive loss
    float bM = b_M[0];
    float lc = 0.f;
    if (tid < BB*TT) {
        int b = tid >> 5, t1 = tid & 31;
        float a1v = a1s[b*TT + t1];
        float sum = 0.f, pos = 0.f;
        for (int t2 = 0; t2 < TT; t2++) {
            float s = a1v + a2s[b*TT + t2] + bM;
            s = fminf(10.f, fmaxf(-10.f, s));
            int d = t1 - t2; if (d < 0) d = -d;
            float wv = expf(s * (1.f/(float)(d + 1)));
            sum += wv;
            if (t2 == t1) pos = wv;
        }
        lc = -logf(pos/(sum + 1e-8f));
    }
    #pragma unroll
    for (int o = 16; o > 0; o >>= 1) lc += __shfl_xor_sync(0xffffffffu, lc, o);
    if (lid == 0) red[warp] = lc;
    __syncthreads();
    if (tid == 0) s_lossc = (red[0] + red[1]) / 64.f;
    __syncthreads();

    // sync loss: warp per (b,t) row of m_prev
    float acc = 0.f;
    for (int row = warp; row < BB*TM1; row += 8) {
        int b = row / TM1, t = row % TM1;
        const float* m = &sm[(b*TT + t)*TWO_F];
        float h[4];
        #pragma unroll
        for (int k = 0; k < 4; k++) {
            int j = lid*4 + k;
            float s = b1[j];
            #pragma unroll 8
            for (int f = 0; f < TWO_F; f++) s = fmaf(m[f], W1[j*TWO_F + f], s);
            h[k] = fmaxf(0.f, s);
        }
        float lg[3];
        #pragma unroll
        for (int c = 0; c < 3; c++) {
            float s = 0.f;
            #pragma unroll
            for (int k = 0; k < 4; k++) s = fmaf(h[k], W2[c*TWO_F + lid*4 + k], s);
            #pragma unroll
            for (int o = 16; o > 0; o >>= 1) s += __shfl_xor_sync(0xffffffffu, s, o);
            lg[c] = s + b2[c];
        }
        float mx = fmaxf(lg[0], fmaxf(lg[1], lg[2]));
        float lse = mx + logf(expf(lg[0]-mx) + expf(lg[1]-mx) + expf(lg[2]-mx));
        if (lid == 0) acc += lse - lg[g_lbl[row]];
    }
    if (lid == 0) red[warp] = acc;
    __syncthreads();
    if (tid == 0) {
        float tot = 0.f;
        #pragma unroll
        for (int w = 0; w < 8; w++) tot += red[w];
        out[BB*II*TWO_F + BB*TWO_F] = s_lossc + tot/(float)(BB*TM1);
    }
    // m_t = m_all[:, T-1]
    if (tid < BB*TWO_F) {
        int b = tid >> 7, f = tid & 127;
        out[BB*II*TWO_F + b*TWO_F + f] = sm[(b*TT + TT-1)*TWO_F + f];
    }
}

// ---------------- launch ----------------
extern "C" void kernel_launch(void* const* d_in, const int* in_sizes, int n_in,
                              void* d_out, int out_size) {
    const float* e      = (const float*)d_in[0];
    // d_in[1] = stockID (identity) unused
    const float* Ws_w   = (const float*)d_in[2];
    const float* Ws_b   = (const float*)d_in[3];
    const float* Wiota  = (const float*)d_in[4];
    const float* w_eta  = (const float*)d_in[5];
    const float* w_M    = (const float*)d_in[6];
    const float* b_M    = (const float*)d_in[7];
    const float* sc_W1  = (const float*)d_in[8];
    const float* sc_b1  = (const float*)d_in[9];
    const float* sc_W2  = (const float*)d_in[10];
    const float* sc_b2  = (const float*)d_in[11];
    const int*   perms  = (const int*)d_in[12];
    const int*   cidx   = (const int*)d_in[13];
    float* out = (float*)d_out;

    zero_kernel<<<64, 256>>>();
    prep_kernel<<<TT*II/256, 256>>>(Wiota, w_eta, perms);
    prepg_kernel<<<1, 256>>>(Ws_w, Ws_b);
    q_kernel<<<BB*TT*II/256, 256>>>(e);
    main_kernel<<<BB*TT*NCHUNK, 256>>>(e, w_eta, out);
    label_kernel<<<BB*TM1, 256>>>(e, cidx);
    finalize_kernel<<<1, 256>>>(w_M, b_M, sc_W1, sc_b1, sc_W2, sc_b2, out);
}

// round 8
// speedup vs baseline: 7.5055x; 4.3680x over previous
#include <cuda_runtime.h>
#include <math.h>

#define BB 2
#define TT 32
#define II 2048
#define FF 64
#define TWO_F 128
#define LL 5
#define TM1 (TT-1)
#define NCHUNK 8
#define CHUNK (II/NCHUNK)   // 256

// ---------------- device scratch (no allocations allowed) ----------------
__device__ float g_q[BB*TT*II*FF];          // q_all = e@G + v, 33.5 MB
__device__ float g_G[FF*FF];                // G = Ws^T Ws (symmetric)
__device__ float g_v[FF];                   // v = Ws^T b
__device__ float g_sums[BB*TT*2*TWO_F];     // per-(b,t) group sums [bt][2][128]
__device__ float g_esums[BB*TT*2];          // per-(b,t) group eta sums
__device__ float g_c[II];                   // c_i = Wiota[i] . w_eta
__device__ unsigned char g_mask[TT*II];     // group membership per (t,i)
__device__ int g_lbl[BB*TM1];               // sync labels
__device__ float g_sloss[BB*TM1];           // per-row sync losses

// ---------------- kernel: zero accumulators ----------------
__global__ void zero_kernel() {
    int idx = blockIdx.x*blockDim.x + threadIdx.x;
    if (idx < BB*TT*2*TWO_F) g_sums[idx] = 0.f;
    if (idx < BB*TT*2)       g_esums[idx] = 0.f;
}

// ---------------- kernel: prep (c_i warp-coalesced + membership mask) ----------------
// grid 64 x 256 (512 warps)
__global__ void prep_kernel(const float* __restrict__ Wiota,
                            const float* __restrict__ w_eta,
                            const int*   __restrict__ perms) {
    int tid = blockIdx.x*blockDim.x + threadIdx.x;
    int wg = tid >> 5, lid = tid & 31;
    float4 e4 = ((const float4*)w_eta)[lid];          // f = 4lid..4lid+3
    for (int r = wg; r < II; r += 512) {
        float4 w4 = ((const float4*)(Wiota + (size_t)r*TWO_F))[lid];
        float p = w4.x*e4.x + w4.y*e4.y + w4.z*e4.z + w4.w*e4.w;
        #pragma unroll
        for (int o = 16; o > 0; o >>= 1) p += __shfl_xor_sync(0xffffffffu, p, o);
        if (lid == 0) g_c[r] = p;
    }
    for (int idx = tid; idx < TT*II; idx += 64*256) {
        int t = idx / II, j = idx % II;
        g_mask[t*II + perms[idx]] = (j < II/2) ? 0 : 1;
    }
}

// ---------------- kernel: G = Ws^T Ws, v = Ws^T b ----------------
__global__ void prepg_kernel(const float* __restrict__ Ww,
                             const float* __restrict__ Wb) {
    int tid = threadIdx.x;
    for (int x = tid; x < FF*FF; x += 256) {
        int j = x >> 6, k = x & 63;
        float s = 0.f;
        #pragma unroll 8
        for (int f = 0; f < FF; f++) s = fmaf(Ww[f*FF + j], Ww[f*FF + k], s);
        g_G[x] = s;
    }
    if (tid < FF) {
        float s = 0.f;
        #pragma unroll 8
        for (int f = 0; f < FF; f++) s = fmaf(Ww[f*FF + tid], Wb[f], s);
        g_v[tid] = s;
    }
}

// ---------------- kernel: q_all = e @ G + v (register-tiled GEMM) ----------------
__global__ void __launch_bounds__(256, 2)
q_kernel(const float* __restrict__ e) {
    __shared__ float  sG[FF][FF+1];
    __shared__ float2 se2[FF][17];
    int tid = threadIdx.x;
    for (int x = tid; x < FF*FF; x += 256) sG[x >> 6][x & 63] = g_G[x];
    int f  = tid & 63;
    int rg = tid >> 6;
    float vf = g_v[f];
    size_t base = (size_t)blockIdx.x * 256;
    for (int it = 0; it < 8; it++) {
        size_t rb = base + it*32;
        __syncthreads();
        for (int x = tid; x < 32*FF; x += 256) {
            int r = x >> 6, k = x & 63;
            ((float*)&se2[k][0])[r] = e[(rb + (size_t)r)*FF + k];
        }
        __syncthreads();
        float2 a0 = {0.f,0.f}, a1 = {0.f,0.f}, a2 = {0.f,0.f}, a3 = {0.f,0.f};
        #pragma unroll
        for (int k = 0; k < FF; k++) {
            float w = sG[k][f];
            float2 e0 = se2[k][rg*4+0];
            float2 e1 = se2[k][rg*4+1];
            float2 e2 = se2[k][rg*4+2];
            float2 e3 = se2[k][rg*4+3];
            a0.x = fmaf(w, e0.x, a0.x); a0.y = fmaf(w, e0.y, a0.y);
            a1.x = fmaf(w, e1.x, a1.x); a1.y = fmaf(w, e1.y, a1.y);
            a2.x = fmaf(w, e2.x, a2.x); a2.y = fmaf(w, e2.y, a2.y);
            a3.x = fmaf(w, e3.x, a3.x); a3.y = fmaf(w, e3.y, a3.y);
        }
        size_t r0 = rb + rg*8;
        g_q[(r0+0)*FF + f] = a0.x + vf;  g_q[(r0+1)*FF + f] = a0.y + vf;
        g_q[(r0+2)*FF + f] = a1.x + vf;  g_q[(r0+3)*FF + f] = a1.y + vf;
        g_q[(r0+4)*FF + f] = a2.x + vf;  g_q[(r0+5)*FF + f] = a2.y + vf;
        g_q[(r0+6)*FF + f] = a3.x + vf;  g_q[(r0+7)*FF + f] = a3.y + vf;
    }
}

// ---------------- kernel: main fused attention + eta + group sums ----------------
__global__ void __launch_bounds__(256, 4)
main_kernel(const float* __restrict__ e,
            const float* __restrict__ w_eta,
            float* __restrict__ out) {
    int bid = blockIdx.x;
    int chunk = bid % NCHUNK;
    int bt = bid / NCHUNK;
    int b = bt / TT, t = bt % TT;
    int warp = threadIdx.x >> 5, lid = threadIdx.x & 31;

    __shared__ float2 wbuf[8][2][64];
    __shared__ float  webuf[8][2];
    for (int x = threadIdx.x; x < 8*2*64; x += 256) {
        ((float2*)wbuf)[x] = make_float2(0.f, 0.f);
    }
    if (threadIdx.x < 16) ((float*)webuf)[threadIdx.x] = 0.f;
    __syncthreads();

    float2 wa = ((const float2*)w_eta)[lid];
    float2 wb = ((const float2*)w_eta)[32 + lid];

    const size_t base_bt = (size_t)(b*TT + t)*II;

    for (int it = 0; it < CHUNK/8; it++) {
        int i = chunk*CHUNK + it*8 + warp;
        float2 q2 = ((const float2*)&g_q[(base_bt + (size_t)i)*FF])[lid];
        float2 wrow[LL];
        #pragma unroll
        for (int l = 0; l < LL; l++) {
            int tl = t - (LL-1) + l;
            int tlc = tl < 0 ? 0 : tl;
            wrow[l] = ((const float2*)&e[((size_t)(b*TT + tlc)*II + (size_t)i)*FF])[lid];
        }
        float sc[LL];
        #pragma unroll
        for (int l = 0; l < LL; l++) {
            float p = q2.x*wrow[l].x + q2.y*wrow[l].y;
            #pragma unroll
            for (int o = 16; o > 0; o >>= 1) p += __shfl_xor_sync(0xffffffffu, p, o);
            int tl = t - (LL-1) + l;
            sc[l] = (tl >= 0) ? p*0.125f : -1e30f;
        }
        float mx = sc[0];
        #pragma unroll
        for (int l = 1; l < LL; l++) mx = fmaxf(mx, sc[l]);
        float den = 0.f, a[LL];
        #pragma unroll
        for (int l = 0; l < LL; l++) { a[l] = expf(sc[l] - mx); den += a[l]; }
        float inv = 1.f/den;

        float2 rh = make_float2(0.f, 0.f);
        #pragma unroll
        for (int l = 0; l < LL; l++) {
            float al = a[l]*inv;
            rh.x = fmaf(al, wrow[l].x, rh.x);
            rh.y = fmaf(al, wrow[l].y, rh.y);
        }
        float2 es = wrow[LL-1];

        float p = es.x*wa.x + es.y*wa.y + rh.x*wb.x + rh.y*wb.y;
        #pragma unroll
        for (int o = 16; o > 0; o >>= 1) p += __shfl_xor_sync(0xffffffffu, p, o);
        float eta = fmaxf(0.f, p + g_c[i]);
        int g = g_mask[t*II + i];
        float2 acc0 = wbuf[warp][g][lid];
        acc0.x = fmaf(eta, es.x, acc0.x);
        acc0.y = fmaf(eta, es.y, acc0.y);
        wbuf[warp][g][lid] = acc0;
        float2 acc1 = wbuf[warp][g][32 + lid];
        acc1.x = fmaf(eta, rh.x, acc1.x);
        acc1.y = fmaf(eta, rh.y, acc1.y);
        wbuf[warp][g][32 + lid] = acc1;
        if (lid == 0) webuf[warp][g] += eta;

        if (t == TT-1) {
            float2* o2 = (float2*)(out + ((size_t)b*II + (size_t)i)*TWO_F);
            o2[lid]      = es;
            o2[32 + lid] = rh;
        }
    }
    __syncthreads();
    int x = threadIdx.x;
    if (x < 128) {
        int g = x >> 6, j = x & 63;
        float2 v = make_float2(0.f, 0.f);
        #pragma unroll
        for (int w = 0; w < 8; w++) {
            float2 u = wbuf[w][g][j];
            v.x += u.x; v.y += u.y;
        }
        atomicAdd(&g_sums[bt*256 + g*128 + 2*j],     v.x);
        atomicAdd(&g_sums[bt*256 + g*128 + 2*j + 1], v.y);
    }
    if (threadIdx.x >= 128 && threadIdx.x < 130) {
        int g = threadIdx.x - 128;
        float s = 0.f;
        #pragma unroll
        for (int w = 0; w < 8; w++) s += webuf[w][g];
        atomicAdd(&g_esums[bt*2 + g], s);
    }
}

// ---------------- kernel: sync labels ----------------
__global__ void label_kernel(const float* __restrict__ e,
                             const int* __restrict__ close_idx) {
    int row = blockIdx.x;
    int b = row / TM1, t = row % TM1;
    int cidx = close_idx[0];
    __shared__ int sp[256], sn[256];
    int cp = 0, cn = 0;
    for (int i = threadIdx.x; i < II; i += 256) {
        float c0 = e[((size_t)(b*TT + t)*II + i)*FF + cidx];
        float c1 = e[((size_t)(b*TT + t + 1)*II + i)*FF + cidx];
        float r = logf(c1/(c0 + 1e-8f));
        cp += (r > 0.f); cn += (r < 0.f);
    }
    sp[threadIdx.x] = cp; sn[threadIdx.x] = cn;
    __syncthreads();
    for (int s = 128; s > 0; s >>= 1) {
        if (threadIdx.x < s) { sp[threadIdx.x] += sp[threadIdx.x+s]; sn[threadIdx.x] += sn[threadIdx.x+s]; }
        __syncthreads();
    }
    if (threadIdx.x == 0) {
        float pr = sp[0]/(float)II, nr = sn[0]/(float)II;
        g_lbl[row] = pr >= 0.6f ? 0 : (nr >= 0.6f ? 1 : 2);
    }
}

// ---------------- kernel: per-row sync loss (parallel MLP) ----------------
// grid = BB*TM1 (62), block = 128
__global__ void sync_kernel(const float* __restrict__ W1,
                            const float* __restrict__ b1,
                            const float* __restrict__ W2,
                            const float* __restrict__ b2) {
    int row = blockIdx.x;               // b*(T-1)+t
    int b = row / TM1, t = row % TM1;
    int bt = b*TT + t;
    int tid = threadIdx.x;
    int lid = tid & 31, warp = tid >> 5;
    __shared__ float sm[TWO_F];
    __shared__ float sh[TWO_F];
    __shared__ float slg[3];

    // m_prev row
    {
        float es = g_esums[bt*2] + g_esums[bt*2 + 1];
        sm[tid] = (g_sums[bt*256 + tid] + g_sums[bt*256 + 128 + tid])/(es + 1e-6f);
    }
    __syncthreads();

    // h_j = relu(b1[j] + m . W1[j,:])   (thread tid owns j = tid)
    {
        const float4* W14 = (const float4*)(W1 + (size_t)tid*TWO_F);
        const float4* sm4 = (const float4*)sm;
        float acc = b1[tid];
        #pragma unroll
        for (int k = 0; k < TWO_F/4; k++) {
            float4 w4 = W14[k];
            float4 m4 = sm4[k];           // broadcast
            acc += w4.x*m4.x + w4.y*m4.y + w4.z*m4.z + w4.w*m4.w;
        }
        sh[tid] = fmaxf(acc, 0.f);
    }
    __syncthreads();

    // logits (warp 0)
    if (warp == 0) {
        const float4* sh4 = (const float4*)sh;
        float4 h4 = sh4[lid];
        #pragma unroll
        for (int c = 0; c < 3; c++) {
            float4 w4 = ((const float4*)(W2 + c*TWO_F))[lid];
            float p = h4.x*w4.x + h4.y*w4.y + h4.z*w4.z + h4.w*w4.w;
            #pragma unroll
            for (int o = 16; o > 0; o >>= 1) p += __shfl_xor_sync(0xffffffffu, p, o);
            if (lid == 0) slg[c] = p + b2[c];
        }
        __syncwarp();
        if (lid == 0) {
            float l0 = slg[0], l1 = slg[1], l2 = slg[2];
            float mx = fmaxf(l0, fmaxf(l1, l2));
            float lse = mx + logf(expf(l0-mx) + expf(l1-mx) + expf(l2-mx));
            g_sloss[row] = lse - slg[g_lbl[row]];
        }
    }
}

// ---------------- kernel: finalize (m_t, contrastive loss, total) ----------------
__global__ void finalize_kernel(const float* __restrict__ w_M,
                                const float* __restrict__ b_M,
                                float* __restrict__ out) {
    __shared__ float a1s[BB*TT], a2s[BB*TT];
    __shared__ float red[8];
    __shared__ float s_sync;
    int tid = threadIdx.x;
    int warp = tid >> 5, lid = tid & 31;

    // a1/a2: l2-normalized subset means dotted with w_M halves. Warp per bt.
    for (int bt = warp; bt < BB*TT; bt += 8) {
        float es1 = g_esums[bt*2] + 1e-6f, es2 = g_esums[bt*2 + 1] + 1e-6f;
        float ss1 = 0.f, d1 = 0.f, ss2 = 0.f, d2 = 0.f;
        #pragma unroll
        for (int k = 0; k < 4; k++) {
            int f = lid + k*32;
            float m1 = g_sums[bt*256 + f]/es1;
            float m2 = g_sums[bt*256 + 128 + f]/es2;
            ss1 = fmaf(m1, m1, ss1); d1 = fmaf(m1, w_M[f], d1);
            ss2 = fmaf(m2, m2, ss2); d2 = fmaf(m2, w_M[128 + f], d2);
        }
        #pragma unroll
        for (int o = 16; o > 0; o >>= 1) {
            ss1 += __shfl_xor_sync(0xffffffffu, ss1, o);
            d1  += __shfl_xor_sync(0xffffffffu, d1,  o);
            ss2 += __shfl_xor_sync(0xffffffffu, ss2, o);
            d2  += __shfl_xor_sync(0xffffffffu, d2,  o);
        }
        if (lid == 0) {
            a1s[bt] = d1/fmaxf(sqrtf(ss1), 1e-12f);
            a2s[bt] = d2/fmaxf(sqrtf(ss2), 1e-12f);
        }
    }
    // sync-loss sum (warp 7, independent of a1s/a2s)
    if (warp == 7) {
        float s = (lid < BB*TM1) ? g_sloss[lid] : 0.f;
        if (lid + 32 < BB*TM1) s += g_sloss[lid + 32];
        #pragma unroll
        for (int o = 16; o > 0; o >>= 1) s += __shfl_xor_sync(0xffffffffu, s, o);
        if (lid == 0) s_sync = s/(float)(BB*TM1);
    }
    __syncthreads();

    // contrastive loss
    float bM = b_M[0];
    float lc = 0.f;
    if (tid < BB*TT) {
        int b = tid >> 5, t1 = tid & 31;
        float a1v = a1s[b*TT + t1];
        float sum = 0.f, pos = 0.f;
        for (int t2 = 0; t2 < TT; t2++) {
            float s = a1v + a2s[b*TT + t2] + bM;
            s = fminf(10.f, fmaxf(-10.f, s));
            int d = t1 - t2; if (d < 0) d = -d;
            float wv = expf(s * (1.f/(float)(d + 1)));
            sum += wv;
            if (t2 == t1) pos = wv;
        }
        lc = -logf(pos/(sum + 1e-8f));
    }
    #pragma unroll
    for (int o = 16; o > 0; o >>= 1) lc += __shfl_xor_sync(0xffffffffu, lc, o);
    if (lid == 0) red[warp] = lc;
    __syncthreads();
    if (tid == 0) {
        out[BB*II*TWO_F + BB*TWO_F] = (red[0] + red[1])/64.f + s_sync;
    }
    // m_t = m_all[:, T-1]
    if (tid < BB*TWO_F) {
        int b = tid >> 7, f = tid & 127;
        int bt = b*TT + TT-1;
        float es = g_esums[bt*2] + g_esums[bt*2 + 1];
        float s  = g_sums[bt*256 + f] + g_sums[bt*256 + 128 + f];
        out[BB*II*TWO_F + b*TWO_F + f] = s/(es + 1e-6f);
    }
}

// ---------------- launch ----------------
extern "C" void kernel_launch(void* const* d_in, const int* in_sizes, int n_in,
                              void* d_out, int out_size) {
    const float* e      = (const float*)d_in[0];
    const float* Ws_w   = (const float*)d_in[2];
    const float* Ws_b   = (const float*)d_in[3];
    const float* Wiota  = (const float*)d_in[4];
    const float* w_eta  = (const float*)d_in[5];
    const float* w_M    = (const float*)d_in[6];
    const float* b_M    = (const float*)d_in[7];
    const float* sc_W1  = (const float*)d_in[8];
    const float* sc_b1  = (const float*)d_in[9];
    const float* sc_W2  = (const float*)d_in[10];
    const float* sc_b2  = (const float*)d_in[11];
    const int*   perms  = (const int*)d_in[12];
    const int*   cidx   = (const int*)d_in[13];
    float* out = (float*)d_out;

    zero_kernel<<<64, 256>>>();
    prep_kernel<<<64, 256>>>(Wiota, w_eta, perms);
    prepg_kernel<<<1, 256>>>(Ws_w, Ws_b);
    q_kernel<<<BB*TT*II/256, 256>>>(e);
    main_kernel<<<BB*TT*NCHUNK, 256>>>(e, w_eta, out);
    label_kernel<<<BB*TM1, 256>>>(e, cidx);
    sync_kernel<<<BB*TM1, 128>>>(sc_W1, sc_b1, sc_W2, sc_b2);
    finalize_kernel<<<1, 256>>>(w_M, b_M, out);
}